// round 1
// baseline (speedup 1.0000x reference)
#include <cuda_runtime.h>
#include <cstdint>

#define BATCH 8
#define NA 3
#define NC 80
#define HH 160
#define WW 160
#define HW 25600      // HH*WW
#define NPB 76800     // NA*HW, candidates per batch
#define TOPKK 100
#define CAP 4096
#define NBIN 4096

typedef unsigned long long u64;
typedef unsigned int u32;

// ---------------- static device scratch (no runtime allocation) ----------------
__device__ u64 g_keys[BATCH * NPB];     // (score_bits<<17)|inv_idx per candidate
__device__ u32 g_hist[BATCH * NBIN];    // per-batch histogram of key>>36 (top 12 bits)
__device__ u64 g_cand[BATCH * CAP];     // collected boundary candidates
__device__ int g_ccount[BATCH];
__device__ u32 g_sel12[BATCH];          // boundary 12-bit bin
__device__ int g_locked[BATCH];         // # keys strictly above boundary bin (<100)

__device__ __forceinline__ float fsig(float x) { return 1.0f / (1.0f + __expf(-x)); }

// ---------------- K0: zero per-launch state ----------------
__global__ void initK() {
    int i = blockIdx.x * blockDim.x + threadIdx.x;
    if (i < BATCH * NBIN) g_hist[i] = 0;
    if (i < BATCH) g_ccount[i] = 0;
}

// ---------------- K1: streaming max-over-classes + score + key + fused histogram ----------------
// grid 600 blocks x 256 threads; each thread owns 4 consecutive pixels (float4 loads).
// 75 blocks per batch (block never straddles a batch or an anchor plane).
__global__ void __launch_bounds__(256) scoreK(const float* __restrict__ obj,
                                              const float* __restrict__ qual,
                                              const float* __restrict__ cls) {
    __shared__ u32 hist[NBIN];
    for (int j = threadIdx.x; j < NBIN; j += 256) hist[j] = 0;
    __syncthreads();

    int bid = blockIdx.x;
    int b = bid / 75;
    int i0 = (bid - b * 75) * 1024 + threadIdx.x * 4;  // candidate index within batch
    int a = i0 / HW;
    int pix = i0 - a * HW;
    int plane = b * NA + a;

    float4 o4 = *reinterpret_cast<const float4*>(obj + (size_t)plane * HW + pix);
    float4 q4 = *reinterpret_cast<const float4*>(qual + (size_t)plane * HW + pix);
    const float* cp = cls + (size_t)plane * NC * HW + pix;

    float m0 = -3.4e38f, m1 = -3.4e38f, m2 = -3.4e38f, m3 = -3.4e38f;
#pragma unroll 8
    for (int c = 0; c < NC; c++) {
        float4 v = *reinterpret_cast<const float4*>(cp + (size_t)c * HW);
        m0 = fmaxf(m0, v.x); m1 = fmaxf(m1, v.y);
        m2 = fmaxf(m2, v.z); m3 = fmaxf(m3, v.w);
    }
    // score = sigmoid(o)*sigmoid(q)*sigmoid(max_logit), fused into one reciprocal
    float s0 = 1.0f / ((1.0f + __expf(-o4.x)) * (1.0f + __expf(-q4.x)) * (1.0f + __expf(-m0)));
    float s1 = 1.0f / ((1.0f + __expf(-o4.y)) * (1.0f + __expf(-q4.y)) * (1.0f + __expf(-m1)));
    float s2 = 1.0f / ((1.0f + __expf(-o4.z)) * (1.0f + __expf(-q4.z)) * (1.0f + __expf(-m2)));
    float s3 = 1.0f / ((1.0f + __expf(-o4.w)) * (1.0f + __expf(-q4.w)) * (1.0f + __expf(-m3)));

    // key: positive-float bit order => score desc; inv_idx => idx asc on ties (matches top_k)
    u64 k0 = ((u64)__float_as_uint(s0) << 17) | (u32)(NPB - 1 - (i0 + 0));
    u64 k1 = ((u64)__float_as_uint(s1) << 17) | (u32)(NPB - 1 - (i0 + 1));
    u64 k2 = ((u64)__float_as_uint(s2) << 17) | (u32)(NPB - 1 - (i0 + 2));
    u64 k3 = ((u64)__float_as_uint(s3) << 17) | (u32)(NPB - 1 - (i0 + 3));

    u64* kp = g_keys + (size_t)b * NPB + i0;
    reinterpret_cast<ulonglong2*>(kp)[0] = make_ulonglong2(k0, k1);
    reinterpret_cast<ulonglong2*>(kp)[1] = make_ulonglong2(k2, k3);

    atomicAdd(&hist[(u32)(k0 >> 36) & (NBIN - 1)], 1u);
    atomicAdd(&hist[(u32)(k1 >> 36) & (NBIN - 1)], 1u);
    atomicAdd(&hist[(u32)(k2 >> 36) & (NBIN - 1)], 1u);
    atomicAdd(&hist[(u32)(k3 >> 36) & (NBIN - 1)], 1u);
    __syncthreads();

    for (int j = threadIdx.x; j < NBIN; j += 256) {
        u32 v = hist[j];
        if (v) atomicAdd(&g_hist[b * NBIN + j], v);
    }
}

// ---------------- K2: find boundary histogram bin per batch ----------------
__global__ void __launch_bounds__(256) selectK() {
    int b = blockIdx.x;
    int t = threadIdx.x;
    __shared__ u32 h[NBIN];
    __shared__ u32 csum[256];
    for (int j = t; j < NBIN; j += 256) h[j] = g_hist[b * NBIN + j];
    __syncthreads();

    u32 s = 0;
#pragma unroll
    for (int q = 0; q < 16; q++) s += h[t * 16 + q];
    csum[t] = s;
    __syncthreads();
    // inclusive suffix sum over 256 chunks (Hillis-Steele)
    for (int d = 1; d < 256; d <<= 1) {
        u32 v = (t + d < 256) ? csum[t + d] : 0u;
        __syncthreads();
        csum[t] += v;
        __syncthreads();
    }
    u32 above = (t < 255) ? csum[t + 1] : 0u;
    if (csum[t] >= TOPKK && above < TOPKK) {   // exactly one thread
        u32 cum = above;
        int d;
        for (d = t * 16 + 15;; d--) {
            if (cum + h[d] >= TOPKK) break;
            cum += h[d];
        }
        g_sel12[b] = (u32)d;
        g_locked[b] = (int)cum;
    }
}

// ---------------- K3: full-bandwidth collect of candidates >= boundary bin ----------------
__global__ void __launch_bounds__(256) collectK() {
    int bid = blockIdx.x;
    int b = bid / 75;
    int i0 = (bid - b * 75) * 1024 + threadIdx.x * 4;
    u32 pfx = g_sel12[b];
    const u64* kp = g_keys + (size_t)b * NPB + i0;
    ulonglong2 p0 = reinterpret_cast<const ulonglong2*>(kp)[0];
    ulonglong2 p1 = reinterpret_cast<const ulonglong2*>(kp)[1];
    u64 ks[4] = {p0.x, p0.y, p1.x, p1.y};
#pragma unroll
    for (int j = 0; j < 4; j++) {
        if ((u32)(ks[j] >> 36) >= pfx) {
            int pos = atomicAdd(&g_ccount[b], 1);
            if (pos < CAP) g_cand[(size_t)b * CAP + pos] = ks[j];
        }
    }
}

// ---------------- K4: per-batch sort, argmax for winners, box decode, output ----------------
__global__ void __launch_bounds__(1024) finalK(const float* __restrict__ box,
                                               const float* __restrict__ cls,
                                               const float* __restrict__ anch,
                                               float* __restrict__ out) {
    int b = blockIdx.x;
    int tid = threadIdx.x;
    __shared__ u64 scand[CAP];                 // 32 KB; aliased as hist in slow path
    __shared__ int s_cnt, s_d, s_locked, s_bucket;

    int M = g_ccount[b];
    int C;
    if (M <= CAP) {
        // fast path: candidates already collected
        C = M;
        for (int j = tid; j < C; j += 1024) scand[j] = g_cand[(size_t)b * CAP + j];
    } else {
        // exact slow path: refine prefix 12 bits at a time over the full key array
        u32* hist = reinterpret_cast<u32*>(scand);              // bytes [0,16K)
        u32* csum2 = reinterpret_cast<u32*>(scand + 2048);      // bytes [16K,20K)
        u64 prefixVal = ((u64)g_sel12[b]) << 36;
        int locked = g_locked[b];
        int shiftFinal = 36;
        for (int lvl = 1; lvl < 4; lvl++) {
            int shift = 36 - 12 * lvl;
            for (int j = tid; j < NBIN; j += 1024) hist[j] = 0;
            __syncthreads();
            u64 maskAbove = ~((((u64)1) << (shift + 12)) - 1);
            for (int j = tid; j < NPB; j += 1024) {
                u64 k = g_keys[(size_t)b * NPB + j];
                if ((k & maskAbove) == prefixVal)
                    atomicAdd(&hist[(u32)(k >> shift) & (NBIN - 1)], 1u);
            }
            __syncthreads();
            u32 s = 0;
#pragma unroll
            for (int q = 0; q < 4; q++) s += hist[tid * 4 + q];
            csum2[tid] = s;
            __syncthreads();
            for (int d = 1; d < 1024; d <<= 1) {
                u32 v = (tid + d < 1024) ? csum2[tid + d] : 0u;
                __syncthreads();
                csum2[tid] += v;
                __syncthreads();
            }
            u32 above = (tid < 1023) ? csum2[tid + 1] : 0u;
            if (locked + (int)csum2[tid] >= TOPKK && locked + (int)above < TOPKK) {
                u32 cum = above;
                int d;
                for (d = tid * 4 + 3;; d--) {
                    if (locked + (int)cum + (int)hist[d] >= TOPKK) break;
                    cum += hist[d];
                }
                s_d = d; s_locked = locked + (int)cum; s_bucket = (int)hist[d];
            }
            __syncthreads();
            locked = s_locked;
            prefixVal |= ((u64)s_d) << shift;
            shiftFinal = shift;
            int bucket = s_bucket;
            __syncthreads();
            if (locked + bucket <= CAP) break;   // guaranteed true by shift==0 (keys distinct)
        }
        if (tid == 0) s_cnt = 0;
        __syncthreads();
        u64 thr = prefixVal >> shiftFinal;
        for (int j = tid; j < NPB; j += 1024) {
            u64 k = g_keys[(size_t)b * NPB + j];
            if ((k >> shiftFinal) >= thr) {
                int pos = atomicAdd(&s_cnt, 1);
                scand[pos] = k;
            }
        }
        __syncthreads();
        C = s_cnt;
    }

    // pad to power of two and bitonic sort descending
    int npow = 128;
    while (npow < C) npow <<= 1;
    for (int j = C + tid; j < npow; j += 1024) scand[j] = 0ull;
    __syncthreads();
    for (int k = 2; k <= npow; k <<= 1) {
        for (int j = k >> 1; j > 0; j >>= 1) {
            for (int i = tid; i < npow; i += 1024) {
                int ixj = i ^ j;
                if (ixj > i) {
                    u64 A = scand[i], Bv = scand[ixj];
                    bool seg = ((i & k) == 0);
                    bool sw = seg ? (A < Bv) : (A > Bv);   // descending overall
                    if (sw) { scand[i] = Bv; scand[ixj] = A; }
                }
            }
            __syncthreads();
        }
    }

    // winners: one warp per rank, 80-class argmax + box decode
    int warp = tid >> 5, lane = tid & 31;
    for (int r = warp; r < TOPKK; r += 32) {
        u64 k = scand[r];
        u32 sb = (u32)(k >> 17);
        int idx = NPB - 1 - (int)(k & 0x1FFFFu);
        int a = idx / HW;
        int pix = idx - a * HW;
        int y = pix / WW;
        int x = pix - y * WW;

        const float* cp = cls + (size_t)(b * NA + a) * NC * HW + pix;
        float bv = -3.4e38f;
        int bc = 0;
        for (int c = lane; c < NC; c += 32) {
            float v = cp[(size_t)c * HW];
            if (v > bv) { bv = v; bc = c; }           // strict > keeps lowest class on ties
        }
#pragma unroll
        for (int off = 16; off; off >>= 1) {
            float ov = __shfl_xor_sync(0xffffffffu, bv, off);
            int oc = __shfl_xor_sync(0xffffffffu, bc, off);
            if (ov > bv || (ov == bv && oc < bc)) { bv = ov; bc = oc; }
        }
        if (lane == 0) {
            const float* bp = box + (size_t)(b * NA + a) * 4 * HW + pix;
            float tx = bp[0];
            float ty = bp[(size_t)HW];
            float tw = bp[2 * (size_t)HW];
            float th = bp[3 * (size_t)HW];
            float aw = anch[a * 2 + 0];
            float ah = anch[a * 2 + 1];
            float cx = (fsig(tx) + (float)x) / (float)WW;
            float cy = (fsig(ty) + (float)y) / (float)HH;
            // faithful softplus: relu(x) + log1p(exp(-|x|))
            float spw = fmaxf(tw, 0.0f) + log1pf(__expf(-fabsf(tw)));
            float sph = fmaxf(th, 0.0f) + log1pf(__expf(-fabsf(th)));
            float* o = out + ((size_t)b * TOPKK + r) * 6;
            o[0] = __uint_as_float(sb);
            o[1] = (float)bc;
            o[2] = cx;
            o[3] = cy;
            o[4] = aw * spw;
            o[5] = ah * sph;
        }
    }
}

// ---------------- launch ----------------
extern "C" void kernel_launch(void* const* d_in, const int* in_sizes, int n_in,
                              void* d_out, int out_size) {
    // expected order: box, obj, quality, cls_logits, anchors — verified by size
    const float* box  = (const float*)d_in[0];
    const float* obj  = (const float*)d_in[1];
    const float* qual = (const float*)d_in[2];
    const float* cls  = (const float*)d_in[3];
    const float* anch = (const float*)d_in[4];
    int seen = 0;
    for (int i = 0; i < n_in; i++) {
        int s = in_sizes[i];
        if (s == BATCH * NA * 4 * HW) box = (const float*)d_in[i];
        else if (s == BATCH * NA * NC * HW) cls = (const float*)d_in[i];
        else if (s == NA * 2) anch = (const float*)d_in[i];
        else if (s == BATCH * NA * HW) {
            if (seen == 0) obj = (const float*)d_in[i];
            else qual = (const float*)d_in[i];
            seen++;
        }
    }
    float* out = (float*)d_out;

    initK<<<(BATCH * NBIN + 255) / 256, 256>>>();
    scoreK<<<600, 256>>>(obj, qual, cls);
    selectK<<<BATCH, 256>>>();
    collectK<<<600, 256>>>();
    finalK<<<BATCH, 1024>>>(box, cls, anch, out);
}